// round 12
// baseline (speedup 1.0000x reference)
#include <cuda_runtime.h>
#include <cuda_fp16.h>

#define H 128
#define HH (H * H)
#define TILE_M 64
#define NTG 256       // 8 warps
#define NT 256
#define MAXN 50176
#define MAXE 800000
#define SCAN_BLK 256
#define XPAD 136      // smem row pitch in halves

typedef unsigned long long ull;

// Scratch (device globals — no allocation allowed)
__device__ __half g_h0h[(size_t)MAXN * H];      // layer-0 activations (fp16)
__device__ __half g_x1h[(size_t)MAXN * H];      // layer-1 activations (fp16)
__device__ int    g_cnt[MAXN];
__device__ int    g_off[MAXN + 1];
__device__ int    g_csr[MAXE];
__device__ int    g_bsum[(MAXN + SCAN_BLK - 1) / SCAN_BLK];

// half helpers
__device__ __forceinline__ uint2 pack4h(float a, float b, float c, float d) {
    uint2 r;
    __half2 h0 = __float22half2_rn(make_float2(a, b));
    __half2 h1 = __float22half2_rn(make_float2(c, d));
    r.x = *(unsigned*)&h0;
    r.y = *(unsigned*)&h1;
    return r;
}

// ---------------------------------------------------------------------------
// CSR build kernels
// ---------------------------------------------------------------------------
__global__ void zero_cnt(int N) {
    int i = blockIdx.x * blockDim.x + threadIdx.x;
    if (i < N) g_cnt[i] = 0;
}

__global__ void deg_hist(const int* __restrict__ ei, int E) {
    int e = blockIdx.x * blockDim.x + threadIdx.x;
    if (e < E) atomicAdd(&g_cnt[ei[E + e]], 1);
}

__global__ void scanA(int N) {
    __shared__ int sh[SCAN_BLK];
    int tid = threadIdx.x;
    int gi = blockIdx.x * SCAN_BLK + tid;
    int v = (gi < N) ? g_cnt[gi] : 0;
    sh[tid] = v;
    __syncthreads();
#pragma unroll
    for (int off = 1; off < SCAN_BLK; off <<= 1) {
        int t = (tid >= off) ? sh[tid - off] : 0;
        __syncthreads();
        sh[tid] += t;
        __syncthreads();
    }
    if (gi < N) g_off[gi] = sh[tid] - v;
    if (tid == SCAN_BLK - 1) g_bsum[blockIdx.x] = sh[tid];
}

__global__ void scanC(int N, int E, int nblk) {
    __shared__ int sh[SCAN_BLK];
    __shared__ int ex[SCAN_BLK];
    int tid = threadIdx.x;
    int v = (tid < nblk) ? g_bsum[tid] : 0;
    sh[tid] = v;
    __syncthreads();
#pragma unroll
    for (int off = 1; off < SCAN_BLK; off <<= 1) {
        int t = (tid >= off) ? sh[tid - off] : 0;
        __syncthreads();
        sh[tid] += t;
        __syncthreads();
    }
    ex[tid] = sh[tid] - v;
    __syncthreads();
    int add = ex[blockIdx.x];
    int gi = blockIdx.x * SCAN_BLK + tid;
    if (gi < N) g_off[gi] += add;
    if (blockIdx.x == 0 && tid == 0) g_off[N] = E;
}

__global__ void csr_fill(const int* __restrict__ ei, int E) {
    int e = blockIdx.x * blockDim.x + threadIdx.x;
    if (e >= E) return;
    int s = ei[e];
    int t = ei[E + e];
    int pos = atomicAdd(&g_cnt[t], -1) - 1;
    g_csr[g_off[t] + pos] = s;
}

// ---------------------------------------------------------------------------
// HMMA warp GEMM core (validated R10): warp computes m16 x n64 over K=128.
// ---------------------------------------------------------------------------
__device__ __forceinline__ void warp_mma(const __half* __restrict__ As,
                                         const __half* __restrict__ Wsm,
                                         int m0, int nbase, int lane,
                                         float c[8][4]) {
    const int g = lane >> 2, tig = lane & 3;
    const __half* arow0 = As + (m0 + g) * XPAD + tig * 2;
    const __half* arow8 = As + (m0 + g + 8) * XPAD + tig * 2;
#pragma unroll
    for (int kc = 0; kc < 8; kc++) {
        unsigned a0 = *(const unsigned*)(arow0 + kc * 16);
        unsigned a1 = *(const unsigned*)(arow8 + kc * 16);
        unsigned a2 = *(const unsigned*)(arow0 + kc * 16 + 8);
        unsigned a3 = *(const unsigned*)(arow8 + kc * 16 + 8);
#pragma unroll
        for (int nt = 0; nt < 8; nt++) {
            const __half* brow = Wsm + (nbase + nt * 8 + g) * XPAD + kc * 16 + tig * 2;
            unsigned b0 = *(const unsigned*)(brow);
            unsigned b1 = *(const unsigned*)(brow + 8);
            asm volatile(
                "mma.sync.aligned.m16n8k16.row.col.f32.f16.f16.f32 "
                "{%0,%1,%2,%3}, {%4,%5,%6,%7}, {%8,%9}, {%0,%1,%2,%3};"
                : "+f"(c[nt][0]), "+f"(c[nt][1]), "+f"(c[nt][2]), "+f"(c[nt][3])
                : "r"(a0), "r"(a1), "r"(a2), "r"(a3), "r"(b0), "r"(b1));
        }
    }
}

// Load fp32 weight [H,H] row-major into smem fp16 [128][XPAD]
__device__ __forceinline__ void fill_w_f32(__half* Wsm, const float* __restrict__ W,
                                           int tid) {
    for (int idx = tid; idx < 128 * 16; idx += NTG) {
        int r = idx >> 4, ch = idx & 15;
        float4 f0 = *(const float4*)(W + r * H + ch * 8);
        float4 f1 = *(const float4*)(W + r * H + ch * 8 + 4);
        uint2 lo = pack4h(f0.x, f0.y, f0.z, f0.w);
        uint2 hi = pack4h(f1.x, f1.y, f1.z, f1.w);
        *(uint4*)(Wsm + r * XPAD + ch * 8) = make_uint4(lo.x, lo.y, hi.x, hi.y);
    }
}

// Load fp16 activation tile into smem [TILE_M][XPAD]
__device__ __forceinline__ void fill_x(__half* Xs, const __half* __restrict__ src,
                                       int nb, int N, int tid) {
    for (int idx = tid; idx < TILE_M * 16; idx += NTG) {
        int r = idx >> 4, ch = idx & 15;
        int gr = nb + r;
        uint4 v = make_uint4(0, 0, 0, 0);
        if (gr < N) v = *(const uint4*)(src + (size_t)gr * H + ch * 8);
        *(uint4*)(Xs + r * XPAD + ch * 8) = v;
    }
}

// ---------------------------------------------------------------------------
// Warp-gather of one node's neighbor mean into smem (fp16).
// ---------------------------------------------------------------------------
__device__ __forceinline__ void hacc(float2& a0, float2& a1, float2& a2,
                                     float2& a3, uint4 v) {
    __half2* p = (__half2*)&v;
    float2 f0 = __half22float2(p[0]);
    float2 f1 = __half22float2(p[1]);
    float2 f2 = __half22float2(p[2]);
    float2 f3 = __half22float2(p[3]);
    a0.x += f0.x; a0.y += f0.y;
    a1.x += f1.x; a1.y += f1.y;
    a2.x += f2.x; a2.y += f2.y;
    a3.x += f3.x; a3.y += f3.y;
}

__device__ __forceinline__ void gather_node_smem(__half* Ag, int nl,
                                                 const __half* __restrict__ h,
                                                 int node, int N, int lane) {
    const int half = lane >> 4;
    const int l = lane & 15;
    const int col = l << 3;

    if (node >= N) {
        if (half == 0) *(uint4*)(Ag + nl * XPAD + col) = make_uint4(0, 0, 0, 0);
        return;
    }
    int beg = g_off[node];
    int end = g_off[node + 1];
    float2 a0 = {0.f, 0.f}, a1 = {0.f, 0.f}, a2 = {0.f, 0.f}, a3 = {0.f, 0.f};

    int i = beg;
    for (; i + 4 <= end; i += 4) {
        int sA = __ldg(&g_csr[i + half]);
        int sB = __ldg(&g_csr[i + 2 + half]);
        uint4 vA = *(const uint4*)(h + (size_t)sA * H + col);
        uint4 vB = *(const uint4*)(h + (size_t)sB * H + col);
        hacc(a0, a1, a2, a3, vA);
        hacc(a0, a1, a2, a3, vB);
    }
    for (; i < end; i += 2) {
        int idx = i + half;
        if (idx < end) {
            int s = __ldg(&g_csr[idx]);
            uint4 v = *(const uint4*)(h + (size_t)s * H + col);
            hacc(a0, a1, a2, a3, v);
        }
    }

    a0.x += __shfl_xor_sync(0xffffffffu, a0.x, 16);
    a0.y += __shfl_xor_sync(0xffffffffu, a0.y, 16);
    a1.x += __shfl_xor_sync(0xffffffffu, a1.x, 16);
    a1.y += __shfl_xor_sync(0xffffffffu, a1.y, 16);
    a2.x += __shfl_xor_sync(0xffffffffu, a2.x, 16);
    a2.y += __shfl_xor_sync(0xffffffffu, a2.y, 16);
    a3.x += __shfl_xor_sync(0xffffffffu, a3.x, 16);
    a3.y += __shfl_xor_sync(0xffffffffu, a3.y, 16);

    if (half == 0) {
        float inv = 1.0f / (float)max(end - beg, 1);
        uint2 lo = pack4h(a0.x * inv, a0.y * inv, a1.x * inv, a1.y * inv);
        uint2 hi = pack4h(a2.x * inv, a2.y * inv, a3.x * inv, a3.y * inv);
        *(uint4*)(Ag + nl * XPAD + col) = make_uint4(lo.x, lo.y, hi.x, hi.y);
    }
}

// ---------------------------------------------------------------------------
// Input layer: h0h = fp16(relu(concat(attr,cc,bl,exist) @ W_in^T + b_in))
// ---------------------------------------------------------------------------
__global__ void __launch_bounds__(NTG)
input_gemm(const float* __restrict__ attr, int ATTR,
           const float* __restrict__ cc,
           const float* __restrict__ bl,
           const float* __restrict__ exist,
           const float* __restrict__ W_in,
           const float* __restrict__ b, int N) {
    extern __shared__ __half sm[];
    __half* Xs = sm;                       // TILE_M * XPAD
    __half* Wsm = sm + TILE_M * XPAD;      // 128 * XPAD
    const int tid = threadIdx.x;
    const int nb = blockIdx.x * TILE_M;

    fill_w_f32(Wsm, W_in, tid);
    for (int idx = tid; idx < TILE_M * H; idx += NTG) {
        int n = idx >> 7, k = idx & 127;
        int gn = nb + n;
        float v = 0.f;
        if (gn < N) {
            if (k < ATTR)            v = attr[(size_t)gn * ATTR + k];
            else if (k == ATTR)      v = cc[gn];
            else if (k == ATTR + 1)  v = bl[gn];
            else if (k == ATTR + 2)  v = exist[gn];
        }
        Xs[n * XPAD + k] = __float2half(v);
    }
    __syncthreads();

    const int wid = tid >> 5, lane = tid & 31;
    const int m0 = (wid & 3) * 16, nbase = (wid >> 2) * 64;
    const int g = lane >> 2, tig = lane & 3;
    float c[8][4] = {};
    warp_mma(Xs, Wsm, m0, nbase, lane, c);

    int r0 = nb + m0 + g, r1 = r0 + 8;
#pragma unroll
    for (int nt = 0; nt < 8; nt++) {
        int col = nbase + nt * 8 + tig * 2;
        float b0 = b[col], b1 = b[col + 1];
        if (r0 < N) {
            float v0 = fmaxf(c[nt][0] + b0, 0.f);
            float v1 = fmaxf(c[nt][1] + b1, 0.f);
            __half2 hv = __float22half2_rn(make_float2(v0, v1));
            *(unsigned*)(g_h0h + (size_t)r0 * H + col) = *(unsigned*)&hv;
        }
        if (r1 < N) {
            float v0 = fmaxf(c[nt][2] + b0, 0.f);
            float v1 = fmaxf(c[nt][3] + b1, 0.f);
            __half2 hv = __float22half2_rn(make_float2(v0, v1));
            *(unsigned*)(g_h0h + (size_t)r1 * H + col) = *(unsigned*)&hv;
        }
    }
}

// ---------------------------------------------------------------------------
// Fused SAGE layer: self-MMA + gather + neigh-MMA (same accumulators) + epilogue
// ---------------------------------------------------------------------------
__global__ void __launch_bounds__(NTG)
sage_layer(int xsel,
           const float* __restrict__ Wself,
           const float* __restrict__ Wneigh,
           const float* __restrict__ bs,
           const float* __restrict__ bn,
           const float* __restrict__ exist,
           float* out, int N, int do_relu) {
    extern __shared__ __half sm[];
    __half* Xs  = sm;                            // TILE_M * XPAD
    __half* Ag  = sm + TILE_M * XPAD;            // TILE_M * XPAD
    __half* Wsm = sm + 2 * TILE_M * XPAD;        // 128 * XPAD
    const int tid = threadIdx.x;
    const int nb = blockIdx.x * TILE_M;
    const int wid = tid >> 5, lane = tid & 31;
    const int m0 = (wid & 3) * 16, nbase = (wid >> 2) * 64;
    const int g = lane >> 2, tig = lane & 3;
    const __half* __restrict__ X = xsel ? g_x1h : g_h0h;

    // phase 1: self MMA
    fill_w_f32(Wsm, Wself, tid);
    fill_x(Xs, X, nb, N, tid);
    __syncthreads();

    float c[8][4] = {};
    warp_mma(Xs, Wsm, m0, nbase, lane, c);
    __syncthreads();

    // phase 2: reload W with Wneigh; gather neighbor means into Ag
    fill_w_f32(Wsm, Wneigh, tid);
#pragma unroll
    for (int i = 0; i < 8; i++) {
        int nl = wid * 8 + i;
        gather_node_smem(Ag, nl, X, nb + nl, N, lane);
    }
    __syncthreads();

    warp_mma(Ag, Wsm, m0, nbase, lane, c);   // accumulate

    // epilogue
    int r0 = nb + m0 + g, r1 = r0 + 8;
    float e0 = (r0 < N) ? exist[r0] : 0.f;
    float e1 = (r1 < N) ? exist[r1] : 0.f;
#pragma unroll
    for (int nt = 0; nt < 8; nt++) {
        int col = nbase + nt * 8 + tig * 2;
        float bb0 = bs[col] + bn[col];
        float bb1 = bs[col + 1] + bn[col + 1];
        if (r0 < N) {
            float v0 = c[nt][0] + bb0;
            float v1 = c[nt][1] + bb1;
            if (do_relu) { v0 = fmaxf(v0, 0.f); v1 = fmaxf(v1, 0.f); }
            v0 *= e0; v1 *= e0;
            if (out) {
                *(float2*)(out + (size_t)r0 * H + col) = make_float2(v0, v1);
            } else {
                __half2 hv = __float22half2_rn(make_float2(v0, v1));
                *(unsigned*)(g_x1h + (size_t)r0 * H + col) = *(unsigned*)&hv;
            }
        }
        if (r1 < N) {
            float v0 = c[nt][2] + bb0;
            float v1 = c[nt][3] + bb1;
            if (do_relu) { v0 = fmaxf(v0, 0.f); v1 = fmaxf(v1, 0.f); }
            v0 *= e1; v1 *= e1;
            if (out) {
                *(float2*)(out + (size_t)r1 * H + col) = make_float2(v0, v1);
            } else {
                __half2 hv = __float22half2_rn(make_float2(v0, v1));
                *(unsigned*)(g_x1h + (size_t)r1 * H + col) = *(unsigned*)&hv;
            }
        }
    }
}

// ---------------------------------------------------------------------------
extern "C" void kernel_launch(void* const* d_in, const int* in_sizes, int n_in,
                              void* d_out, int out_size) {
    const float* attr  = (const float*)d_in[0];
    const float* cc    = (const float*)d_in[1];
    const float* bl    = (const float*)d_in[2];
    const float* exist = (const float*)d_in[3];
    const float* W_in  = (const float*)d_in[4];
    const float* b_in  = (const float*)d_in[5];
    const float* W1s   = (const float*)d_in[6];
    const float* b1s   = (const float*)d_in[7];
    const float* W1n   = (const float*)d_in[8];
    const float* b1n   = (const float*)d_in[9];
    const float* W2s   = (const float*)d_in[10];
    const float* b2s   = (const float*)d_in[11];
    const float* W2n   = (const float*)d_in[12];
    const float* b2n   = (const float*)d_in[13];
    const int*   ei    = (const int*)d_in[14];   // int32 (JAX x64 disabled)

    const int N    = in_sizes[3];
    const int ATTR = in_sizes[0] / N;
    const int E    = in_sizes[14] / 2;
    float* out = (float*)d_out;

    static cudaStream_t s1 = nullptr;
    static cudaEvent_t evFork, evCSR;
    if (!s1) {
        cudaStreamCreateWithFlags(&s1, cudaStreamNonBlocking);
        cudaEventCreateWithFlags(&evFork, cudaEventDisableTiming);
        cudaEventCreateWithFlags(&evCSR,  cudaEventDisableTiming);
    }

    const int SMEM_IN = (TILE_M + 128) * XPAD * (int)sizeof(__half);       // ~52KB
    const int SMEM_LY = (2 * TILE_M + 128) * XPAD * (int)sizeof(__half);   // ~70KB
    cudaFuncSetAttribute(input_gemm, cudaFuncAttributeMaxDynamicSharedMemorySize, SMEM_IN);
    cudaFuncSetAttribute(sage_layer, cudaFuncAttributeMaxDynamicSharedMemorySize, SMEM_LY);

    const int G = (N + TILE_M - 1) / TILE_M;
    const int edge_grid = (E + NT - 1) / NT;
    const int node_grid = (N + NT - 1) / NT;
    const int scan_grid = (N + SCAN_BLK - 1) / SCAN_BLK;
    cudaStream_t ms = (cudaStream_t)0;

    // Legal capture fork: s1 must wait on an event recorded in the capturing
    // stream before receiving any work.
    cudaEventRecord(evFork, ms);
    cudaStreamWaitEvent(s1, evFork, 0);

    // s1: CSR build chain
    zero_cnt<<<node_grid, NT, 0, s1>>>(N);
    deg_hist<<<edge_grid, NT, 0, s1>>>(ei, E);
    scanA<<<scan_grid, SCAN_BLK, 0, s1>>>(N);
    scanC<<<scan_grid, SCAN_BLK, 0, s1>>>(N, E, scan_grid);
    csr_fill<<<edge_grid, NT, 0, s1>>>(ei, E);
    cudaEventRecord(evCSR, s1);

    // main: input GEMM overlaps CSR build
    input_gemm<<<G, NTG, SMEM_IN, ms>>>(attr, ATTR, cc, bl, exist, W_in, b_in, N);

    // layers (each fused: self-MMA + gather + neigh-MMA + epilogue)
    cudaStreamWaitEvent(ms, evCSR, 0);
    sage_layer<<<G, NTG, SMEM_LY, ms>>>(0, W1s, W1n, b1s, b1n, exist, nullptr, N, 1);
    sage_layer<<<G, NTG, SMEM_LY, ms>>>(1, W2s, W2n, b2s, b2n, exist, out, N, 0);
}

// round 13
// speedup vs baseline: 1.2735x; 1.2735x over previous
#include <cuda_runtime.h>
#include <cuda_fp16.h>

#define H 128
#define HH (H * H)
#define TILE_M 64
#define NTG 512       // 16 warps
#define NT 256
#define MAXN 50176
#define MAXE 800000
#define SCAN_BLK 256
#define XPAD 136      // smem row pitch in halves

// Scratch (device globals — no allocation allowed)
__device__ __half g_h0h[(size_t)MAXN * H];      // layer-0 activations (fp16)
__device__ __half g_x1h[(size_t)MAXN * H];      // layer-1 activations (fp16)
__device__ int    g_cnt[MAXN];
__device__ int    g_off[MAXN + 1];
__device__ int    g_csr[MAXE];
__device__ int    g_bsum[(MAXN + SCAN_BLK - 1) / SCAN_BLK];

// half helpers
__device__ __forceinline__ uint2 pack4h(float a, float b, float c, float d) {
    uint2 r;
    __half2 h0 = __float22half2_rn(make_float2(a, b));
    __half2 h1 = __float22half2_rn(make_float2(c, d));
    r.x = *(unsigned*)&h0;
    r.y = *(unsigned*)&h1;
    return r;
}

// ---------------------------------------------------------------------------
// CSR build kernels
// ---------------------------------------------------------------------------
__global__ void zero_cnt(int N) {
    int i = blockIdx.x * blockDim.x + threadIdx.x;
    if (i < N) g_cnt[i] = 0;
}

__global__ void deg_hist(const int* __restrict__ ei, int E) {
    int e = blockIdx.x * blockDim.x + threadIdx.x;
    if (e < E) atomicAdd(&g_cnt[ei[E + e]], 1);
}

__global__ void scanA(int N) {
    __shared__ int sh[SCAN_BLK];
    int tid = threadIdx.x;
    int gi = blockIdx.x * SCAN_BLK + tid;
    int v = (gi < N) ? g_cnt[gi] : 0;
    sh[tid] = v;
    __syncthreads();
#pragma unroll
    for (int off = 1; off < SCAN_BLK; off <<= 1) {
        int t = (tid >= off) ? sh[tid - off] : 0;
        __syncthreads();
        sh[tid] += t;
        __syncthreads();
    }
    if (gi < N) g_off[gi] = sh[tid] - v;
    if (tid == SCAN_BLK - 1) g_bsum[blockIdx.x] = sh[tid];
}

__global__ void scanC(int N, int E, int nblk) {
    __shared__ int sh[SCAN_BLK];
    __shared__ int ex[SCAN_BLK];
    int tid = threadIdx.x;
    int v = (tid < nblk) ? g_bsum[tid] : 0;
    sh[tid] = v;
    __syncthreads();
#pragma unroll
    for (int off = 1; off < SCAN_BLK; off <<= 1) {
        int t = (tid >= off) ? sh[tid - off] : 0;
        __syncthreads();
        sh[tid] += t;
        __syncthreads();
    }
    ex[tid] = sh[tid] - v;
    __syncthreads();
    int add = ex[blockIdx.x];
    int gi = blockIdx.x * SCAN_BLK + tid;
    if (gi < N) g_off[gi] += add;
    if (blockIdx.x == 0 && tid == 0) g_off[N] = E;
}

__global__ void csr_fill(const int* __restrict__ ei, int E) {
    int e = blockIdx.x * blockDim.x + threadIdx.x;
    if (e >= E) return;
    int s = ei[e];
    int t = ei[E + e];
    int pos = atomicAdd(&g_cnt[t], -1) - 1;
    g_csr[g_off[t] + pos] = s;
}

// ---------------------------------------------------------------------------
// HMMA warp GEMM core: warp computes m16 x n32 over K=128 (4 n8-tiles).
// A from As [.][XPAD] (row-major m,k); B from Wsm [128][XPAD] ([n][k]).
// ---------------------------------------------------------------------------
__device__ __forceinline__ void warp_mma32(const __half* __restrict__ As,
                                           const __half* __restrict__ Wsm,
                                           int m0, int nbase, int lane,
                                           float c[4][4]) {
    const int g = lane >> 2, tig = lane & 3;
    const __half* arow0 = As + (m0 + g) * XPAD + tig * 2;
    const __half* arow8 = As + (m0 + g + 8) * XPAD + tig * 2;
#pragma unroll
    for (int kc = 0; kc < 8; kc++) {
        unsigned a0 = *(const unsigned*)(arow0 + kc * 16);
        unsigned a1 = *(const unsigned*)(arow8 + kc * 16);
        unsigned a2 = *(const unsigned*)(arow0 + kc * 16 + 8);
        unsigned a3 = *(const unsigned*)(arow8 + kc * 16 + 8);
#pragma unroll
        for (int nt = 0; nt < 4; nt++) {
            const __half* brow = Wsm + (nbase + nt * 8 + g) * XPAD + kc * 16 + tig * 2;
            unsigned b0 = *(const unsigned*)(brow);
            unsigned b1 = *(const unsigned*)(brow + 8);
            asm volatile(
                "mma.sync.aligned.m16n8k16.row.col.f32.f16.f16.f32 "
                "{%0,%1,%2,%3}, {%4,%5,%6,%7}, {%8,%9}, {%0,%1,%2,%3};"
                : "+f"(c[nt][0]), "+f"(c[nt][1]), "+f"(c[nt][2]), "+f"(c[nt][3])
                : "r"(a0), "r"(a1), "r"(a2), "r"(a3), "r"(b0), "r"(b1));
        }
    }
}

// Load fp32 weight [H,H] row-major into smem fp16 [128][XPAD]
__device__ __forceinline__ void fill_w_f32(__half* Wsm, const float* __restrict__ W,
                                           int tid) {
    for (int idx = tid; idx < 128 * 16; idx += NTG) {
        int r = idx >> 4, ch = idx & 15;
        float4 f0 = *(const float4*)(W + r * H + ch * 8);
        float4 f1 = *(const float4*)(W + r * H + ch * 8 + 4);
        uint2 lo = pack4h(f0.x, f0.y, f0.z, f0.w);
        uint2 hi = pack4h(f1.x, f1.y, f1.z, f1.w);
        *(uint4*)(Wsm + r * XPAD + ch * 8) = make_uint4(lo.x, lo.y, hi.x, hi.y);
    }
}

// Load fp16 activation tile into smem [TILE_M][XPAD]
__device__ __forceinline__ void fill_x(__half* Xs, const __half* __restrict__ src,
                                       int nb, int N, int tid) {
    for (int idx = tid; idx < TILE_M * 16; idx += NTG) {
        int r = idx >> 4, ch = idx & 15;
        int gr = nb + r;
        uint4 v = make_uint4(0, 0, 0, 0);
        if (gr < N) v = *(const uint4*)(src + (size_t)gr * H + ch * 8);
        *(uint4*)(Xs + r * XPAD + ch * 8) = v;
    }
}

// ---------------------------------------------------------------------------
// Warp-gather of one node's neighbor mean into smem row nl (fp16).
// Lanes 0-15 even edges, 16-31 odd; fp32 accumulate; shfl combine.
// ---------------------------------------------------------------------------
__device__ __forceinline__ void hacc(float2& a0, float2& a1, float2& a2,
                                     float2& a3, uint4 v) {
    __half2* p = (__half2*)&v;
    float2 f0 = __half22float2(p[0]);
    float2 f1 = __half22float2(p[1]);
    float2 f2 = __half22float2(p[2]);
    float2 f3 = __half22float2(p[3]);
    a0.x += f0.x; a0.y += f0.y;
    a1.x += f1.x; a1.y += f1.y;
    a2.x += f2.x; a2.y += f2.y;
    a3.x += f3.x; a3.y += f3.y;
}

__device__ __forceinline__ void gather_node_smem(__half* Ag, int nl,
                                                 const __half* __restrict__ h,
                                                 int node, int N, int lane) {
    const int half = lane >> 4;
    const int l = lane & 15;
    const int col = l << 3;

    if (node >= N) {
        if (half == 0) *(uint4*)(Ag + nl * XPAD + col) = make_uint4(0, 0, 0, 0);
        return;
    }
    int beg = g_off[node];
    int end = g_off[node + 1];
    float2 a0 = {0.f, 0.f}, a1 = {0.f, 0.f}, a2 = {0.f, 0.f}, a3 = {0.f, 0.f};

    int i = beg;
    for (; i + 4 <= end; i += 4) {
        int sA = __ldg(&g_csr[i + half]);
        int sB = __ldg(&g_csr[i + 2 + half]);
        uint4 vA = *(const uint4*)(h + (size_t)sA * H + col);
        uint4 vB = *(const uint4*)(h + (size_t)sB * H + col);
        hacc(a0, a1, a2, a3, vA);
        hacc(a0, a1, a2, a3, vB);
    }
    for (; i < end; i += 2) {
        int idx = i + half;
        if (idx < end) {
            int s = __ldg(&g_csr[idx]);
            uint4 v = *(const uint4*)(h + (size_t)s * H + col);
            hacc(a0, a1, a2, a3, v);
        }
    }

    a0.x += __shfl_xor_sync(0xffffffffu, a0.x, 16);
    a0.y += __shfl_xor_sync(0xffffffffu, a0.y, 16);
    a1.x += __shfl_xor_sync(0xffffffffu, a1.x, 16);
    a1.y += __shfl_xor_sync(0xffffffffu, a1.y, 16);
    a2.x += __shfl_xor_sync(0xffffffffu, a2.x, 16);
    a2.y += __shfl_xor_sync(0xffffffffu, a2.y, 16);
    a3.x += __shfl_xor_sync(0xffffffffu, a3.x, 16);
    a3.y += __shfl_xor_sync(0xffffffffu, a3.y, 16);

    if (half == 0) {
        float inv = 1.0f / (float)max(end - beg, 1);
        uint2 lo = pack4h(a0.x * inv, a0.y * inv, a1.x * inv, a1.y * inv);
        uint2 hi = pack4h(a2.x * inv, a2.y * inv, a3.x * inv, a3.y * inv);
        *(uint4*)(Ag + nl * XPAD + col) = make_uint4(lo.x, lo.y, hi.x, hi.y);
    }
}

// ---------------------------------------------------------------------------
// Input layer: h0h = fp16(relu(concat(attr,cc,bl,exist) @ W_in^T + b_in))
// ---------------------------------------------------------------------------
__global__ void __launch_bounds__(NTG, 2)
input_gemm(const float* __restrict__ attr, int ATTR,
           const float* __restrict__ cc,
           const float* __restrict__ bl,
           const float* __restrict__ exist,
           const float* __restrict__ W_in,
           const float* __restrict__ b, int N) {
    extern __shared__ __half sm[];
    __half* Xs = sm;                       // TILE_M * XPAD
    __half* Wsm = sm + TILE_M * XPAD;      // 128 * XPAD
    const int tid = threadIdx.x;
    const int nb = blockIdx.x * TILE_M;

    fill_w_f32(Wsm, W_in, tid);
    for (int idx = tid; idx < TILE_M * H; idx += NTG) {
        int n = idx >> 7, k = idx & 127;
        int gn = nb + n;
        float v = 0.f;
        if (gn < N) {
            if (k < ATTR)            v = attr[(size_t)gn * ATTR + k];
            else if (k == ATTR)      v = cc[gn];
            else if (k == ATTR + 1)  v = bl[gn];
            else if (k == ATTR + 2)  v = exist[gn];
        }
        Xs[n * XPAD + k] = __float2half(v);
    }
    __syncthreads();

    const int wid = tid >> 5, lane = tid & 31;
    const int m0 = (wid & 3) * 16, nbase = (wid >> 2) * 32;
    const int g = lane >> 2, tig = lane & 3;
    float c[4][4] = {};
    warp_mma32(Xs, Wsm, m0, nbase, lane, c);

    int r0 = nb + m0 + g, r1 = r0 + 8;
#pragma unroll
    for (int nt = 0; nt < 4; nt++) {
        int col = nbase + nt * 8 + tig * 2;
        float b0 = b[col], b1 = b[col + 1];
        if (r0 < N) {
            float v0 = fmaxf(c[nt][0] + b0, 0.f);
            float v1 = fmaxf(c[nt][1] + b1, 0.f);
            __half2 hv = __float22half2_rn(make_float2(v0, v1));
            *(unsigned*)(g_h0h + (size_t)r0 * H + col) = *(unsigned*)&hv;
        }
        if (r1 < N) {
            float v0 = fmaxf(c[nt][2] + b0, 0.f);
            float v1 = fmaxf(c[nt][3] + b1, 0.f);
            __half2 hv = __float22half2_rn(make_float2(v0, v1));
            *(unsigned*)(g_h0h + (size_t)r1 * H + col) = *(unsigned*)&hv;
        }
    }
}

// ---------------------------------------------------------------------------
// Fused SAGE layer (v2): self-MMA, then gather REUSES the X smem buffer,
// then neigh-MMA accumulates into same fragments, epilogue.
// 512 threads, m16n32 warp tiles -> 2 blocks/SM, 32 warps/SM during gather.
// ---------------------------------------------------------------------------
__global__ void __launch_bounds__(NTG, 2)
sage_layer(int xsel,
           const float* __restrict__ Wself,
           const float* __restrict__ Wneigh,
           const float* __restrict__ bs,
           const float* __restrict__ bn,
           const float* __restrict__ exist,
           float* out, int N, int do_relu) {
    extern __shared__ __half sm[];
    __half* Xs  = sm;                            // TILE_M * XPAD (reused as Ag)
    __half* Wsm = sm + TILE_M * XPAD;            // 128 * XPAD
    const int tid = threadIdx.x;
    const int nb = blockIdx.x * TILE_M;
    const int wid = tid >> 5, lane = tid & 31;
    const int m0 = (wid & 3) * 16, nbase = (wid >> 2) * 32;
    const int g = lane >> 2, tig = lane & 3;
    const __half* __restrict__ X = xsel ? g_x1h : g_h0h;

    // phase 1: self MMA
    fill_w_f32(Wsm, Wself, tid);
    fill_x(Xs, X, nb, N, tid);
    __syncthreads();

    float c[4][4] = {};
    warp_mma32(Xs, Wsm, m0, nbase, lane, c);
    __syncthreads();   // everyone done reading Xs/Wsm

    // phase 2: reload W with Wneigh; gather neighbor means into Xs (reuse)
    fill_w_f32(Wsm, Wneigh, tid);
#pragma unroll
    for (int i = 0; i < 4; i++) {
        int nl = wid * 4 + i;
        gather_node_smem(Xs, nl, X, nb + nl, N, lane);
    }
    __syncthreads();

    warp_mma32(Xs, Wsm, m0, nbase, lane, c);   // accumulate

    // epilogue
    int r0 = nb + m0 + g, r1 = r0 + 8;
    float e0 = (r0 < N) ? exist[r0] : 0.f;
    float e1 = (r1 < N) ? exist[r1] : 0.f;
#pragma unroll
    for (int nt = 0; nt < 4; nt++) {
        int col = nbase + nt * 8 + tig * 2;
        float bb0 = bs[col] + bn[col];
        float bb1 = bs[col + 1] + bn[col + 1];
        if (r0 < N) {
            float v0 = c[nt][0] + bb0;
            float v1 = c[nt][1] + bb1;
            if (do_relu) { v0 = fmaxf(v0, 0.f); v1 = fmaxf(v1, 0.f); }
            v0 *= e0; v1 *= e0;
            if (out) {
                *(float2*)(out + (size_t)r0 * H + col) = make_float2(v0, v1);
            } else {
                __half2 hv = __float22half2_rn(make_float2(v0, v1));
                *(unsigned*)(g_x1h + (size_t)r0 * H + col) = *(unsigned*)&hv;
            }
        }
        if (r1 < N) {
            float v0 = c[nt][2] + bb0;
            float v1 = c[nt][3] + bb1;
            if (do_relu) { v0 = fmaxf(v0, 0.f); v1 = fmaxf(v1, 0.f); }
            v0 *= e1; v1 *= e1;
            if (out) {
                *(float2*)(out + (size_t)r1 * H + col) = make_float2(v0, v1);
            } else {
                __half2 hv = __float22half2_rn(make_float2(v0, v1));
                *(unsigned*)(g_x1h + (size_t)r1 * H + col) = *(unsigned*)&hv;
            }
        }
    }
}

// ---------------------------------------------------------------------------
extern "C" void kernel_launch(void* const* d_in, const int* in_sizes, int n_in,
                              void* d_out, int out_size) {
    const float* attr  = (const float*)d_in[0];
    const float* cc    = (const float*)d_in[1];
    const float* bl    = (const float*)d_in[2];
    const float* exist = (const float*)d_in[3];
    const float* W_in  = (const float*)d_in[4];
    const float* b_in  = (const float*)d_in[5];
    const float* W1s   = (const float*)d_in[6];
    const float* b1s   = (const float*)d_in[7];
    const float* W1n   = (const float*)d_in[8];
    const float* b1n   = (const float*)d_in[9];
    const float* W2s   = (const float*)d_in[10];
    const float* b2s   = (const float*)d_in[11];
    const float* W2n   = (const float*)d_in[12];
    const float* b2n   = (const float*)d_in[13];
    const int*   ei    = (const int*)d_in[14];   // int32 (JAX x64 disabled)

    const int N    = in_sizes[3];
    const int ATTR = in_sizes[0] / N;
    const int E    = in_sizes[14] / 2;
    float* out = (float*)d_out;

    static cudaStream_t s1 = nullptr;
    static cudaEvent_t evFork, evCSR;
    if (!s1) {
        cudaStreamCreateWithFlags(&s1, cudaStreamNonBlocking);
        cudaEventCreateWithFlags(&evFork, cudaEventDisableTiming);
        cudaEventCreateWithFlags(&evCSR,  cudaEventDisableTiming);
    }

    const int SMEM = (TILE_M + 128) * XPAD * (int)sizeof(__half);   // ~52KB
    cudaFuncSetAttribute(input_gemm, cudaFuncAttributeMaxDynamicSharedMemorySize, SMEM);
    cudaFuncSetAttribute(sage_layer, cudaFuncAttributeMaxDynamicSharedMemorySize, SMEM);

    const int G = (N + TILE_M - 1) / TILE_M;
    const int edge_grid = (E + NT - 1) / NT;
    const int node_grid = (N + NT - 1) / NT;
    const int scan_grid = (N + SCAN_BLK - 1) / SCAN_BLK;
    cudaStream_t ms = (cudaStream_t)0;

    // Legal capture fork
    cudaEventRecord(evFork, ms);
    cudaStreamWaitEvent(s1, evFork, 0);

    // s1: CSR build chain (fully independent of main)
    zero_cnt<<<node_grid, NT, 0, s1>>>(N);
    deg_hist<<<edge_grid, NT, 0, s1>>>(ei, E);
    scanA<<<scan_grid, SCAN_BLK, 0, s1>>>(N);
    scanC<<<scan_grid, SCAN_BLK, 0, s1>>>(N, E, scan_grid);
    csr_fill<<<edge_grid, NT, 0, s1>>>(ei, E);
    cudaEventRecord(evCSR, s1);

    // main: input GEMM overlaps CSR build
    input_gemm<<<G, NTG, SMEM, ms>>>(attr, ATTR, cc, bl, exist, W_in, b_in, N);

    // fused layers
    cudaStreamWaitEvent(ms, evCSR, 0);
    sage_layer<<<G, NTG, SMEM, ms>>>(0, W1s, W1n, b1s, b1n, exist, nullptr, N, 1);
    sage_layer<<<G, NTG, SMEM, ms>>>(1, W2s, W2n, b2s, b2n, exist, out, N, 0);
}

// round 14
// speedup vs baseline: 1.2791x; 1.0043x over previous
#include <cuda_runtime.h>
#include <cuda_fp16.h>

#define H 128
#define HH (H * H)
#define TILE_M 64
#define NTG 512       // 16 warps
#define NT 256
#define MAXN 50176
#define MAXE 800000
#define SCAN_BLK 256
#define XPAD 136      // smem row pitch in halves

// Scratch (device globals — no allocation allowed)
// NOTE: g_cnt is zero at the start of every kernel_launch call: it is
// zero-initialized at module load, and csr_fill decrements each counter
// from deg back to exactly 0 on every run (deg-0 nodes are never touched).
__device__ __half g_h0h[(size_t)MAXN * H];      // layer-0 activations (fp16)
__device__ __half g_x1h[(size_t)MAXN * H];      // layer-1 activations (fp16)
__device__ int    g_cnt[MAXN];
__device__ int    g_off[MAXN + 1];
__device__ int    g_csr[MAXE];
__device__ int    g_bsum[(MAXN + SCAN_BLK - 1) / SCAN_BLK];

// half helpers
__device__ __forceinline__ uint2 pack4h(float a, float b, float c, float d) {
    uint2 r;
    __half2 h0 = __float22half2_rn(make_float2(a, b));
    __half2 h1 = __float22half2_rn(make_float2(c, d));
    r.x = *(unsigned*)&h0;
    r.y = *(unsigned*)&h1;
    return r;
}

// ---------------------------------------------------------------------------
// CSR build kernels
// ---------------------------------------------------------------------------
__global__ void deg_hist(const int* __restrict__ ei, int E) {
    int e = blockIdx.x * blockDim.x + threadIdx.x;
    if (e < E) atomicAdd(&g_cnt[ei[E + e]], 1);
}

__global__ void scanA(int N) {
    __shared__ int sh[SCAN_BLK];
    int tid = threadIdx.x;
    int gi = blockIdx.x * SCAN_BLK + tid;
    int v = (gi < N) ? g_cnt[gi] : 0;
    sh[tid] = v;
    __syncthreads();
#pragma unroll
    for (int off = 1; off < SCAN_BLK; off <<= 1) {
        int t = (tid >= off) ? sh[tid - off] : 0;
        __syncthreads();
        sh[tid] += t;
        __syncthreads();
    }
    if (gi < N) g_off[gi] = sh[tid] - v;
    if (tid == SCAN_BLK - 1) g_bsum[blockIdx.x] = sh[tid];
}

__global__ void scanC(int N, int E, int nblk) {
    __shared__ int sh[SCAN_BLK];
    __shared__ int ex[SCAN_BLK];
    int tid = threadIdx.x;
    int v = (tid < nblk) ? g_bsum[tid] : 0;
    sh[tid] = v;
    __syncthreads();
#pragma unroll
    for (int off = 1; off < SCAN_BLK; off <<= 1) {
        int t = (tid >= off) ? sh[tid - off] : 0;
        __syncthreads();
        sh[tid] += t;
        __syncthreads();
    }
    ex[tid] = sh[tid] - v;
    __syncthreads();
    int add = ex[blockIdx.x];
    int gi = blockIdx.x * SCAN_BLK + tid;
    if (gi < N) g_off[gi] += add;
    if (blockIdx.x == 0 && tid == 0) g_off[N] = E;
}

__global__ void csr_fill(const int* __restrict__ ei, int E) {
    int e = blockIdx.x * blockDim.x + threadIdx.x;
    if (e >= E) return;
    int s = ei[e];
    int t = ei[E + e];
    int pos = atomicAdd(&g_cnt[t], -1) - 1;    // restores g_cnt[t] to 0
    g_csr[g_off[t] + pos] = s;
}

// ---------------------------------------------------------------------------
// HMMA warp GEMM core: warp computes m16 x n32 over K=128 (4 n8-tiles).
// ---------------------------------------------------------------------------
__device__ __forceinline__ void warp_mma32(const __half* __restrict__ As,
                                           const __half* __restrict__ Wsm,
                                           int m0, int nbase, int lane,
                                           float c[4][4]) {
    const int g = lane >> 2, tig = lane & 3;
    const __half* arow0 = As + (m0 + g) * XPAD + tig * 2;
    const __half* arow8 = As + (m0 + g + 8) * XPAD + tig * 2;
#pragma unroll
    for (int kc = 0; kc < 8; kc++) {
        unsigned a0 = *(const unsigned*)(arow0 + kc * 16);
        unsigned a1 = *(const unsigned*)(arow8 + kc * 16);
        unsigned a2 = *(const unsigned*)(arow0 + kc * 16 + 8);
        unsigned a3 = *(const unsigned*)(arow8 + kc * 16 + 8);
#pragma unroll
        for (int nt = 0; nt < 4; nt++) {
            const __half* brow = Wsm + (nbase + nt * 8 + g) * XPAD + kc * 16 + tig * 2;
            unsigned b0 = *(const unsigned*)(brow);
            unsigned b1 = *(const unsigned*)(brow + 8);
            asm volatile(
                "mma.sync.aligned.m16n8k16.row.col.f32.f16.f16.f32 "
                "{%0,%1,%2,%3}, {%4,%5,%6,%7}, {%8,%9}, {%0,%1,%2,%3};"
                : "+f"(c[nt][0]), "+f"(c[nt][1]), "+f"(c[nt][2]), "+f"(c[nt][3])
                : "r"(a0), "r"(a1), "r"(a2), "r"(a3), "r"(b0), "r"(b1));
        }
    }
}

// Load fp32 weight [H,H] row-major into smem fp16 [128][XPAD]
__device__ __forceinline__ void fill_w_f32(__half* Wsm, const float* __restrict__ W,
                                           int tid) {
    for (int idx = tid; idx < 128 * 16; idx += NTG) {
        int r = idx >> 4, ch = idx & 15;
        float4 f0 = *(const float4*)(W + r * H + ch * 8);
        float4 f1 = *(const float4*)(W + r * H + ch * 8 + 4);
        uint2 lo = pack4h(f0.x, f0.y, f0.z, f0.w);
        uint2 hi = pack4h(f1.x, f1.y, f1.z, f1.w);
        *(uint4*)(Wsm + r * XPAD + ch * 8) = make_uint4(lo.x, lo.y, hi.x, hi.y);
    }
}

// Load fp16 activation tile into smem [TILE_M][XPAD]
__device__ __forceinline__ void fill_x(__half* Xs, const __half* __restrict__ src,
                                       int nb, int N, int tid) {
    for (int idx = tid; idx < TILE_M * 16; idx += NTG) {
        int r = idx >> 4, ch = idx & 15;
        int gr = nb + r;
        uint4 v = make_uint4(0, 0, 0, 0);
        if (gr < N) v = *(const uint4*)(src + (size_t)gr * H + ch * 8);
        *(uint4*)(Xs + r * XPAD + ch * 8) = v;
    }
}

// ---------------------------------------------------------------------------
// Warp-gather of one node's neighbor mean into smem row nl (fp16).
// Lanes 0-15 even edges, 16-31 odd; MLP=4 main loop (8 edges/iter).
// ---------------------------------------------------------------------------
__device__ __forceinline__ void hacc(float2& a0, float2& a1, float2& a2,
                                     float2& a3, uint4 v) {
    __half2* p = (__half2*)&v;
    float2 f0 = __half22float2(p[0]);
    float2 f1 = __half22float2(p[1]);
    float2 f2 = __half22float2(p[2]);
    float2 f3 = __half22float2(p[3]);
    a0.x += f0.x; a0.y += f0.y;
    a1.x += f1.x; a1.y += f1.y;
    a2.x += f2.x; a2.y += f2.y;
    a3.x += f3.x; a3.y += f3.y;
}

__device__ __forceinline__ void gather_node_smem(__half* Ag, int nl,
                                                 const __half* __restrict__ h,
                                                 int node, int N, int lane) {
    const int half = lane >> 4;
    const int l = lane & 15;
    const int col = l << 3;

    if (node >= N) {
        if (half == 0) *(uint4*)(Ag + nl * XPAD + col) = make_uint4(0, 0, 0, 0);
        return;
    }
    int beg = g_off[node];
    int end = g_off[node + 1];
    float2 a0 = {0.f, 0.f}, a1 = {0.f, 0.f}, a2 = {0.f, 0.f}, a3 = {0.f, 0.f};

    int i = beg;
    // main loop: 8 edges/iter, 4 independent row loads per lane (MLP=4)
    for (; i + 8 <= end; i += 8) {
        int sA = __ldg(&g_csr[i + half]);
        int sB = __ldg(&g_csr[i + 2 + half]);
        int sC = __ldg(&g_csr[i + 4 + half]);
        int sD = __ldg(&g_csr[i + 6 + half]);
        uint4 vA = *(const uint4*)(h + (size_t)sA * H + col);
        uint4 vB = *(const uint4*)(h + (size_t)sB * H + col);
        uint4 vC = *(const uint4*)(h + (size_t)sC * H + col);
        uint4 vD = *(const uint4*)(h + (size_t)sD * H + col);
        hacc(a0, a1, a2, a3, vA);
        hacc(a0, a1, a2, a3, vB);
        hacc(a0, a1, a2, a3, vC);
        hacc(a0, a1, a2, a3, vD);
    }
    for (; i + 4 <= end; i += 4) {
        int sA = __ldg(&g_csr[i + half]);
        int sB = __ldg(&g_csr[i + 2 + half]);
        uint4 vA = *(const uint4*)(h + (size_t)sA * H + col);
        uint4 vB = *(const uint4*)(h + (size_t)sB * H + col);
        hacc(a0, a1, a2, a3, vA);
        hacc(a0, a1, a2, a3, vB);
    }
    for (; i < end; i += 2) {
        int idx = i + half;
        if (idx < end) {
            int s = __ldg(&g_csr[idx]);
            uint4 v = *(const uint4*)(h + (size_t)s * H + col);
            hacc(a0, a1, a2, a3, v);
        }
    }

    a0.x += __shfl_xor_sync(0xffffffffu, a0.x, 16);
    a0.y += __shfl_xor_sync(0xffffffffu, a0.y, 16);
    a1.x += __shfl_xor_sync(0xffffffffu, a1.x, 16);
    a1.y += __shfl_xor_sync(0xffffffffu, a1.y, 16);
    a2.x += __shfl_xor_sync(0xffffffffu, a2.x, 16);
    a2.y += __shfl_xor_sync(0xffffffffu, a2.y, 16);
    a3.x += __shfl_xor_sync(0xffffffffu, a3.x, 16);
    a3.y += __shfl_xor_sync(0xffffffffu, a3.y, 16);

    if (half == 0) {
        float inv = 1.0f / (float)max(end - beg, 1);
        uint2 lo = pack4h(a0.x * inv, a0.y * inv, a1.x * inv, a1.y * inv);
        uint2 hi = pack4h(a2.x * inv, a2.y * inv, a3.x * inv, a3.y * inv);
        *(uint4*)(Ag + nl * XPAD + col) = make_uint4(lo.x, lo.y, hi.x, hi.y);
    }
}

// ---------------------------------------------------------------------------
// Input layer: h0h = fp16(relu(concat(attr,cc,bl,exist) @ W_in^T + b_in))
// ---------------------------------------------------------------------------
__global__ void __launch_bounds__(NTG, 2)
input_gemm(const float* __restrict__ attr, int ATTR,
           const float* __restrict__ cc,
           const float* __restrict__ bl,
           const float* __restrict__ exist,
           const float* __restrict__ W_in,
           const float* __restrict__ b, int N) {
    extern __shared__ __half sm[];
    __half* Xs = sm;                       // TILE_M * XPAD
    __half* Wsm = sm + TILE_M * XPAD;      // 128 * XPAD
    const int tid = threadIdx.x;
    const int nb = blockIdx.x * TILE_M;

    fill_w_f32(Wsm, W_in, tid);
    for (int idx = tid; idx < TILE_M * H; idx += NTG) {
        int n = idx >> 7, k = idx & 127;
        int gn = nb + n;
        float v = 0.f;
        if (gn < N) {
            if (k < ATTR)            v = attr[(size_t)gn * ATTR + k];
            else if (k == ATTR)      v = cc[gn];
            else if (k == ATTR + 1)  v = bl[gn];
            else if (k == ATTR + 2)  v = exist[gn];
        }
        Xs[n * XPAD + k] = __float2half(v);
    }
    __syncthreads();

    const int wid = tid >> 5, lane = tid & 31;
    const int m0 = (wid & 3) * 16, nbase = (wid >> 2) * 32;
    const int g = lane >> 2, tig = lane & 3;
    float c[4][4] = {};
    warp_mma32(Xs, Wsm, m0, nbase, lane, c);

    int r0 = nb + m0 + g, r1 = r0 + 8;
#pragma unroll
    for (int nt = 0; nt < 4; nt++) {
        int col = nbase + nt * 8 + tig * 2;
        float b0 = b[col], b1 = b[col + 1];
        if (r0 < N) {
            float v0 = fmaxf(c[nt][0] + b0, 0.f);
            float v1 = fmaxf(c[nt][1] + b1, 0.f);
            __half2 hv = __float22half2_rn(make_float2(v0, v1));
            *(unsigned*)(g_h0h + (size_t)r0 * H + col) = *(unsigned*)&hv;
        }
        if (r1 < N) {
            float v0 = fmaxf(c[nt][2] + b0, 0.f);
            float v1 = fmaxf(c[nt][3] + b1, 0.f);
            __half2 hv = __float22half2_rn(make_float2(v0, v1));
            *(unsigned*)(g_h0h + (size_t)r1 * H + col) = *(unsigned*)&hv;
        }
    }
}

// ---------------------------------------------------------------------------
// Fused SAGE layer: self-MMA, gather (reuses X smem), neigh-MMA, epilogue.
// ---------------------------------------------------------------------------
__global__ void __launch_bounds__(NTG, 2)
sage_layer(int xsel,
           const float* __restrict__ Wself,
           const float* __restrict__ Wneigh,
           const float* __restrict__ bs,
           const float* __restrict__ bn,
           const float* __restrict__ exist,
           float* out, int N, int do_relu) {
    extern __shared__ __half sm[];
    __half* Xs  = sm;                            // TILE_M * XPAD (reused as Ag)
    __half* Wsm = sm + TILE_M * XPAD;            // 128 * XPAD
    const int tid = threadIdx.x;
    const int nb = blockIdx.x * TILE_M;
    const int wid = tid >> 5, lane = tid & 31;
    const int m0 = (wid & 3) * 16, nbase = (wid >> 2) * 32;
    const int g = lane >> 2, tig = lane & 3;
    const __half* __restrict__ X = xsel ? g_x1h : g_h0h;

    // phase 1: self MMA
    fill_w_f32(Wsm, Wself, tid);
    fill_x(Xs, X, nb, N, tid);
    __syncthreads();

    float c[4][4] = {};
    warp_mma32(Xs, Wsm, m0, nbase, lane, c);
    __syncthreads();

    // phase 2: reload W with Wneigh; gather neighbor means into Xs (reuse)
    fill_w_f32(Wsm, Wneigh, tid);
#pragma unroll
    for (int i = 0; i < 4; i++) {
        int nl = wid * 4 + i;
        gather_node_smem(Xs, nl, X, nb + nl, N, lane);
    }
    __syncthreads();

    warp_mma32(Xs, Wsm, m0, nbase, lane, c);   // accumulate

    // epilogue
    int r0 = nb + m0 + g, r1 = r0 + 8;
    float e0 = (r0 < N) ? exist[r0] : 0.f;
    float e1 = (r1 < N) ? exist[r1] : 0.f;
#pragma unroll
    for (int nt = 0; nt < 4; nt++) {
        int col = nbase + nt * 8 + tig * 2;
        float bb0 = bs[col] + bn[col];
        float bb1 = bs[col + 1] + bn[col + 1];
        if (r0 < N) {
            float v0 = c[nt][0] + bb0;
            float v1 = c[nt][1] + bb1;
            if (do_relu) { v0 = fmaxf(v0, 0.f); v1 = fmaxf(v1, 0.f); }
            v0 *= e0; v1 *= e0;
            if (out) {
                *(float2*)(out + (size_t)r0 * H + col) = make_float2(v0, v1);
            } else {
                __half2 hv = __float22half2_rn(make_float2(v0, v1));
                *(unsigned*)(g_x1h + (size_t)r0 * H + col) = *(unsigned*)&hv;
            }
        }
        if (r1 < N) {
            float v0 = c[nt][2] + bb0;
            float v1 = c[nt][3] + bb1;
            if (do_relu) { v0 = fmaxf(v0, 0.f); v1 = fmaxf(v1, 0.f); }
            v0 *= e1; v1 *= e1;
            if (out) {
                *(float2*)(out + (size_t)r1 * H + col) = make_float2(v0, v1);
            } else {
                __half2 hv = __float22half2_rn(make_float2(v0, v1));
                *(unsigned*)(g_x1h + (size_t)r1 * H + col) = *(unsigned*)&hv;
            }
        }
    }
}

// ---------------------------------------------------------------------------
extern "C" void kernel_launch(void* const* d_in, const int* in_sizes, int n_in,
                              void* d_out, int out_size) {
    const float* attr  = (const float*)d_in[0];
    const float* cc    = (const float*)d_in[1];
    const float* bl    = (const float*)d_in[2];
    const float* exist = (const float*)d_in[3];
    const float* W_in  = (const float*)d_in[4];
    const float* b_in  = (const float*)d_in[5];
    const float* W1s   = (const float*)d_in[6];
    const float* b1s   = (const float*)d_in[7];
    const float* W1n   = (const float*)d_in[8];
    const float* b1n   = (const float*)d_in[9];
    const float* W2s   = (const float*)d_in[10];
    const float* b2s   = (const float*)d_in[11];
    const float* W2n   = (const float*)d_in[12];
    const float* b2n   = (const float*)d_in[13];
    const int*   ei    = (const int*)d_in[14];   // int32 (JAX x64 disabled)

    const int N    = in_sizes[3];
    const int ATTR = in_sizes[0] / N;
    const int E    = in_sizes[14] / 2;
    float* out = (float*)d_out;

    static cudaStream_t s1 = nullptr;
    static cudaEvent_t evFork, evCSR;
    if (!s1) {
        cudaStreamCreateWithFlags(&s1, cudaStreamNonBlocking);
        cudaEventCreateWithFlags(&evFork, cudaEventDisableTiming);
        cudaEventCreateWithFlags(&evCSR,  cudaEventDisableTiming);
    }

    const int SMEM = (TILE_M + 128) * XPAD * (int)sizeof(__half);   // ~52KB
    cudaFuncSetAttribute(input_gemm, cudaFuncAttributeMaxDynamicSharedMemorySize, SMEM);
    cudaFuncSetAttribute(sage_layer, cudaFuncAttributeMaxDynamicSharedMemorySize, SMEM);

    const int G = (N + TILE_M - 1) / TILE_M;
    const int edge_grid = (E + NT - 1) / NT;
    const int scan_grid = (N + SCAN_BLK - 1) / SCAN_BLK;
    cudaStream_t ms = (cudaStream_t)0;

    // Legal capture fork
    cudaEventRecord(evFork, ms);
    cudaStreamWaitEvent(s1, evFork, 0);

    // s1: CSR build chain (g_cnt is already zero — see note at globals)
    deg_hist<<<edge_grid, NT, 0, s1>>>(ei, E);
    scanA<<<scan_grid, SCAN_BLK, 0, s1>>>(N);
    scanC<<<scan_grid, SCAN_BLK, 0, s1>>>(N, E, scan_grid);
    csr_fill<<<edge_grid, NT, 0, s1>>>(ei, E);
    cudaEventRecord(evCSR, s1);

    // main: input GEMM overlaps CSR build
    input_gemm<<<G, NTG, SMEM, ms>>>(attr, ATTR, cc, bl, exist, W_in, b_in, N);

    // fused layers
    cudaStreamWaitEvent(ms, evCSR, 0);
    sage_layer<<<G, NTG, SMEM, ms>>>(0, W1s, W1n, b1s, b1n, exist, nullptr, N, 1);
    sage_layer<<<G, NTG, SMEM, ms>>>(1, W2s, W2n, b2s, b2n, exist, out, N, 0);
}